// round 15
// baseline (speedup 1.0000x reference)
#include <cuda_runtime.h>
#include <math.h>

#define NN 20000
#define EE 320000
#define FF 128
#define KORD 32

// ---------------- device scratch (static: no allocations allowed) ----------------
__device__ __align__(16) float d_B[3][NN * 64];      // Clenshaw b-state ring (N x 64)
__device__ __align__(16) float d_bias[64];
__device__ __align__(16) float d_Wc[KORD * FF * 64]; // packed [W_xz[k] | W_xh[k]] per k
__device__ int   d_rowptr[NN + 1];
__device__ int   d_cnt[NN];
__device__ int   d_fill[NN];
__device__ int   d_deg[NN];
__device__ __align__(16) int2 d_edge[EE];            // (src, weight-bits) per CSR slot
__device__ float d_xp[NN * 32];
__device__ float d_as[NN];
__device__ float d_ad[NN];
__device__ float d_sv[NN];
__device__ float d_tv[NN];
__device__ float d_pq[66];   // [0..31]=p, [32..63]=q, [64]=cs+b_cls, [65]=ct
// software grid barrier state (reset every kernel_launch in k_zero)
__device__ unsigned int d_bar_count;
__device__ volatile unsigned int d_bar_gen;

// ---- packed f32x2 helpers (Blackwell dual-FMA pipe) ----
#define PACK2(dst, lo, hi) \
    asm("mov.b64 %0, {%1, %2};" : "=l"(dst) : "r"(__float_as_uint(lo)), "r"(__float_as_uint(hi)))
#define DUP2(dst, v) \
    asm("mov.b64 %0, {%1, %1};" : "=l"(dst) : "r"(__float_as_uint(v)))
#define FMA2(acc, a, b) \
    asm("fma.rn.f32x2 %0, %1, %2, %0;" : "+l"(acc) : "l"(a), "l"(b))
#define UNPACK2(lo, hi, v) do { unsigned int _ulo, _uhi; \
    asm("mov.b64 {%0, %1}, %2;" : "=r"(_ulo), "=r"(_uhi) : "l"(v)); \
    lo = __uint_as_float(_ulo); hi = __uint_as_float(_uhi); } while (0)

// ---------------- setup kernels ----------------
__global__ void k_zero() {
    int i = blockIdx.x * blockDim.x + threadIdx.x;
    if (i < NN) { d_deg[i] = 0; d_cnt[i] = 0; d_fill[i] = 0; }
    if (i == 0) { d_bar_count = 0; d_bar_gen = 0; }
}

__global__ void k_count(const int* __restrict__ src, const int* __restrict__ dst) {
    int e = blockIdx.x * blockDim.x + threadIdx.x;
    if (e < EE) {
        atomicAdd(&d_deg[src[e]], 1);
        atomicAdd(&d_cnt[dst[e]], 1);
    }
}

// single block, 1024 threads, 20 elements per thread + one Hillis-Steele pass
#define SCAN_CHUNK 20
__global__ void k_scan() {
    __shared__ int tot[1024];
    int tid = threadIdx.x;
    int base = tid * SCAN_CHUNK;
    int loc[SCAN_CHUNK];
    int s = 0;
    #pragma unroll
    for (int i = 0; i < SCAN_CHUNK; i++) {
        int idx = base + i;
        int v = (idx < NN) ? d_cnt[idx] : 0;
        loc[i] = s;
        s += v;
    }
    tot[tid] = s;
    __syncthreads();
    for (int off = 1; off < 1024; off <<= 1) {
        int t = (tid >= off) ? tot[tid - off] : 0;
        __syncthreads();
        tot[tid] += t;
        __syncthreads();
    }
    int excl = tot[tid] - s;
    #pragma unroll
    for (int i = 0; i < SCAN_CHUNK; i++) {
        int idx = base + i;
        if (idx < NN) d_rowptr[idx] = excl + loc[i];
    }
    if (tid == 1023) d_rowptr[NN] = tot[1023];
}

// CSR fill with inline symmetric-normalized weight:
// w = -1/sqrt(deg[s]) * 1/sqrt(deg[d]); deg[s] >= 1 since s sources edge e.
__global__ void k_fill(const int* __restrict__ src, const int* __restrict__ dst) {
    int e = blockIdx.x * blockDim.x + threadIdx.x;
    if (e < EE) {
        int d = dst[e], s = src[e];
        int pos = d_rowptr[d] + atomicAdd(&d_fill[d], 1);
        int degs = d_deg[s], degd = d_deg[d];
        float ws = 1.0f / sqrtf((float)degs);
        float wd = (degd > 0) ? (1.0f / sqrtf((float)degd)) : 0.0f;
        d_edge[pos] = make_int2(s, __float_as_int(-ws * wd));
    }
}

// warp-per-row rank sort (by src key) in shared memory: deterministic order.
#define SORT_CAP 128
__global__ void k_sortrows() {
    __shared__ int skey[8][SORT_CAP];
    __shared__ int sval[8][SORT_CAP];
    int wrp = threadIdx.x >> 5, lane = threadIdx.x & 31;
    int row = blockIdx.x * 8 + wrp;
    if (row >= NN) return;
    int rs = d_rowptr[row], re = d_rowptr[row + 1];
    int d = re - rs;
    if (d <= 1) return;
    if (d > SORT_CAP) {                 // practically unreachable fallback
        if (lane == 0) {
            for (int a = rs + 1; a < re; a++) {
                int2 key = d_edge[a];
                int b = a - 1;
                while (b >= rs && d_edge[b].x > key.x) {
                    d_edge[b + 1] = d_edge[b]; b--;
                }
                d_edge[b + 1] = key;
            }
        }
        return;
    }
    for (int i = lane; i < d; i += 32) {
        int2 q = d_edge[rs + i];
        skey[wrp][i] = q.x;
        sval[wrp][i] = q.y;
    }
    __syncwarp();
    for (int i = lane; i < d; i += 32) {
        int k = skey[wrp][i];
        int r = 0;
        for (int j = 0; j < d; j++) {
            int kj = skey[wrp][j];
            r += (kj < k) || (kj == k && j < i);
        }
        d_edge[rs + r] = make_int2(k, sval[wrp][i]);
    }
}

// merged weight-prep: blocks 0..31 pack Wc_k; block 32 bias; block 33 pq scalars
__global__ void k_weights(const float* __restrict__ Wxz, const float* __restrict__ Wxh,
                          const float* __restrict__ bxz, const float* __restrict__ bhz,
                          const float* __restrict__ bxh, const float* __restrict__ bhh,
                          const float* __restrict__ Wemb, const float* __restrict__ bemb,
                          const float* __restrict__ Wcls, const float* __restrict__ bcls) {
    int b = blockIdx.x;
    if (b < KORD) {
        const float* Wz = Wxz + b * FF * 32;
        const float* Wh = Wxh + b * FF * 32;
        float* out = d_Wc + b * FF * 64;
        for (int idx = threadIdx.x; idx < FF * 64; idx += blockDim.x) {
            int c = idx >> 6, j = idx & 63;
            out[idx] = (j < 32) ? __ldg(&Wz[c * 32 + j]) : __ldg(&Wh[c * 32 + j - 32]);
        }
    } else if (b == KORD) {
        int j = threadIdx.x;
        if (j < 32) d_bias[j] = bxz[j] + bhz[j];
        else if (j < 64) d_bias[j] = bxh[j - 32] + bhh[j - 32];
    } else {
        int t = threadIdx.x;
        if (t < 32) {
            float s = 0.f;
            for (int d = 0; d < 128; d++) s += Wemb[t * 128 + d] * Wcls[d];
            d_pq[t] = s;
        } else if (t < 64) {
            int j = t - 32; float s = 0.f;
            for (int d = 0; d < 128; d++) s += Wemb[j * 128 + d] * Wcls[128 + d];
            d_pq[32 + j] = s;
        } else if (t == 64) {
            float s = 0.f;
            for (int d = 0; d < 128; d++) s += bemb[d] * Wcls[d];
            d_pq[64] = s + bcls[0];
        } else if (t == 65) {
            float s = 0.f;
            for (int d = 0; d < 128; d++) s += bemb[d] * Wcls[128 + d];
            d_pq[65] = s;
        }
    }
}

// ---------------- persistent Clenshaw kernel + fused GRU/GAT-linear tail ----
// b_k = 2*Lhat*b_{k+1} - b_{k+2} + X*Wc_k   (k = 31 .. 1;  b_32 = b_33 = 0)
// out = 1*Lhat*b_1 - b_2 + X*Wc_0 + bias    (k = 0, kept in smem sP)
// tail: z/h gates -> h -> xp = h @ W_gat -> d_xp, d_as, d_ad  (own nodes only)
// Tile = 68 nodes -> grid 295 = EXACTLY one wave at 2 blocks/SM on 148 SMs.
#define CB_NODES 68
#define CB_THREADS 512
#define CB_GRID 295

__global__ void __launch_bounds__(CB_THREADS, 2)
cheb_persistent(const float* __restrict__ x,
                const float* __restrict__ Wg,
                const float* __restrict__ a_src,
                const float* __restrict__ a_dst)
{
    extern __shared__ float sm[];
    float* sX = sm;                        // 68 x 128  (loop-invariant)
    float* sW = sX + CB_NODES * FF;        // 128 x 64
    float* sP = sW + FF * 64;              // 68 x 64
    const int tid  = threadIdx.x;
    const int lane = tid & 31;
    const int wrp  = tid >> 5;             // 0..15
    const int nb   = blockIdx.x * CB_NODES;

    // stage x tile ONCE (loop-invariant) and Wc for the first step (k=31)
    #pragma unroll
    for (int rep = 0; rep < 5; rep++) {
        int li = rep * 16 + wrp;
        if (li >= CB_NODES) break;
        int node = nb + li;
        float4 v = make_float4(0.f, 0.f, 0.f, 0.f);
        if (node < NN) v = __ldg((const float4*)&x[node * FF + lane * 4]);
        *(float4*)&sX[li * FF + lane * 4] = v;
    }
    {
        const float4* Wsrc = (const float4*)(d_Wc + (KORD - 1) * FF * 64);
        float4* Wdst = (float4*)sW;
        #pragma unroll
        for (int r = 0; r < 4; r++) {
            int idx = r * CB_THREADS + tid;     // 2048 float4s
            Wdst[idx] = __ldg(&Wsrc[idx]);
        }
    }

    for (int k = KORD - 1; k >= 0; k--) {
        const int gsel  = (k <= 30) ? (k + 1) % 3 : -1;   // buffer holding b_{k+1}
        const int ppsel = (k <= 29) ? (k + 2) % 3 : -1;   // buffer holding b_{k+2}
        const int nsel  = (k >= 1) ? (k % 3) : -1;        // write b_k (smem at k=0)
        const float coef = (k == 0) ? 1.f : 2.f;

        // gather phase: prop rows of b_{k+1}; warp per node, lane = 2 cols.
        // d_B is mutable across steps: read L2-only (__ldcg) to dodge stale L1.
        if (gsel >= 0) {
            const float* Bg = d_B[gsel];
            #pragma unroll
            for (int rep = 0; rep < 5; rep++) {
                int li = rep * 16 + wrp;
                if (li >= CB_NODES) break;
                int node = nb + li;
                float2 a = make_float2(0.f, 0.f);
                if (node < NN) {
                    int rs = d_rowptr[node], re = d_rowptr[node + 1];
                    int e = rs;
                    for (; e + 4 <= re; e += 4) {
                        int2 q0 = __ldg(&d_edge[e]);
                        int2 q1 = __ldg(&d_edge[e + 1]);
                        int2 q2 = __ldg(&d_edge[e + 2]);
                        int2 q3 = __ldg(&d_edge[e + 3]);
                        float2 v0 = __ldcg((const float2*)&Bg[q0.x * 64 + lane * 2]);
                        float2 v1 = __ldcg((const float2*)&Bg[q1.x * 64 + lane * 2]);
                        float2 v2 = __ldcg((const float2*)&Bg[q2.x * 64 + lane * 2]);
                        float2 v3 = __ldcg((const float2*)&Bg[q3.x * 64 + lane * 2]);
                        float w0 = __int_as_float(q0.y), w1 = __int_as_float(q1.y);
                        float w2 = __int_as_float(q2.y), w3 = __int_as_float(q3.y);
                        a.x += w0 * v0.x + w1 * v1.x + w2 * v2.x + w3 * v3.x;
                        a.y += w0 * v0.y + w1 * v1.y + w2 * v2.y + w3 * v3.y;
                    }
                    for (; e < re; e++) {
                        int2 q = __ldg(&d_edge[e]);
                        float2 v = __ldcg((const float2*)&Bg[q.x * 64 + lane * 2]);
                        float w = __int_as_float(q.y);
                        a.x += w * v.x; a.y += w * v.y;
                    }
                }
                *(float2*)&sP[li * 64 + lane * 2] = a;
            }
        }
        __syncthreads();    // sP + sW ready for all threads

        // GEMM (sX @ sW) + Clenshaw combine + store, packed f32x2 accumulators.
        const int tx = tid & 15, ty = tid >> 4;
        const int r0 = ty * 2, j0 = tx * 4;
        const int node0 = nb + r0, node1 = nb + r0 + 1;

        float4 pre0 = make_float4(0.f, 0.f, 0.f, 0.f);
        float4 pre1 = make_float4(0.f, 0.f, 0.f, 0.f);
        if (ppsel >= 0) {
            if (node0 < NN) pre0 = __ldcg((const float4*)&d_B[ppsel][node0 * 64 + j0]);
            if (node1 < NN) pre1 = __ldcg((const float4*)&d_B[ppsel][node1 * 64 + j0]);
            pre0.x = -pre0.x; pre0.y = -pre0.y; pre0.z = -pre0.z; pre0.w = -pre0.w;
            pre1.x = -pre1.x; pre1.y = -pre1.y; pre1.z = -pre1.z; pre1.w = -pre1.w;
        }
        if (nsel < 0) {  // k == 0: add bias
            float4 bb = *(const float4*)&d_bias[j0];
            pre0.x += bb.x; pre0.y += bb.y; pre0.z += bb.z; pre0.w += bb.w;
            pre1.x += bb.x; pre1.y += bb.y; pre1.z += bb.z; pre1.w += bb.w;
        }

        unsigned long long c00, c01, c10, c11;
        PACK2(c00, pre0.x, pre0.y);
        PACK2(c01, pre0.z, pre0.w);
        PACK2(c10, pre1.x, pre1.y);
        PACK2(c11, pre1.z, pre1.w);

        const float* rowA = &sX[(r0 + 0) * FF];
        const float* rowB = &sX[(r0 + 1) * FF];
        #pragma unroll 8
        for (int kk = 0; kk < 128; kk += 4) {
            float4 vA = *(const float4*)&rowA[kk];
            float4 vB = *(const float4*)&rowB[kk];
            ulonglong2 b0 = *(const ulonglong2*)&sW[(kk + 0) * 64 + j0];
            ulonglong2 b1 = *(const ulonglong2*)&sW[(kk + 1) * 64 + j0];
            ulonglong2 b2 = *(const ulonglong2*)&sW[(kk + 2) * 64 + j0];
            ulonglong2 b3 = *(const ulonglong2*)&sW[(kk + 3) * 64 + j0];
            unsigned long long a;
            DUP2(a, vA.x); FMA2(c00, a, b0.x); FMA2(c01, a, b0.y);
            DUP2(a, vA.y); FMA2(c00, a, b1.x); FMA2(c01, a, b1.y);
            DUP2(a, vA.z); FMA2(c00, a, b2.x); FMA2(c01, a, b2.y);
            DUP2(a, vA.w); FMA2(c00, a, b3.x); FMA2(c01, a, b3.y);
            DUP2(a, vB.x); FMA2(c10, a, b0.x); FMA2(c11, a, b0.y);
            DUP2(a, vB.y); FMA2(c10, a, b1.x); FMA2(c11, a, b1.y);
            DUP2(a, vB.z); FMA2(c10, a, b2.x); FMA2(c11, a, b2.y);
            DUP2(a, vB.w); FMA2(c10, a, b3.x); FMA2(c11, a, b3.y);
        }

        float4 acc0, acc1;
        UNPACK2(acc0.x, acc0.y, c00);
        UNPACK2(acc0.z, acc0.w, c01);
        UNPACK2(acc1.x, acc1.y, c10);
        UNPACK2(acc1.z, acc1.w, c11);

        #pragma unroll
        for (int i = 0; i < 2; i++) {
            int node = nb + r0 + i;
            if (node >= NN) continue;
            float4 val = (i == 0) ? acc0 : acc1;
            if (gsel >= 0) {
                float4 p = *(const float4*)&sP[(r0 + i) * 64 + j0];
                val.x += coef * p.x; val.y += coef * p.y;
                val.z += coef * p.z; val.w += coef * p.w;
            }
            if (nsel >= 0) *(float4*)&d_B[nsel][node * 64 + j0] = val;
            else           *(float4*)&sP[(r0 + i) * 64 + j0]    = val;  // k=0: keep in smem
        }

        // Remainder pass: rows 64..67, threads 0..127 take 1 row x 2 cols each.
        if (tid < 128) {
            int er = 64 + (tid >> 5);              // 64..67
            int ej = (tid & 31) * 2;               // even col 0..62
            int enode = nb + er;
            if (enode < NN) {
                float2 pre = make_float2(0.f, 0.f);
                if (ppsel >= 0) {
                    float2 t = __ldcg((const float2*)&d_B[ppsel][enode * 64 + ej]);
                    pre.x = -t.x; pre.y = -t.y;
                }
                if (nsel < 0) { pre.x += d_bias[ej]; pre.y += d_bias[ej + 1]; }
                unsigned long long cc;
                PACK2(cc, pre.x, pre.y);
                const float* rowE = &sX[er * FF];
                #pragma unroll 8
                for (int kk = 0; kk < 128; kk++) {
                    unsigned long long a, b;
                    DUP2(a, rowE[kk]);
                    b = *(const unsigned long long*)&sW[kk * 64 + ej];
                    FMA2(cc, a, b);
                }
                float2 val;
                UNPACK2(val.x, val.y, cc);
                if (gsel >= 0) {
                    float2 p = *(const float2*)&sP[er * 64 + ej];
                    val.x += coef * p.x; val.y += coef * p.y;
                }
                if (nsel >= 0) *(float2*)&d_B[nsel][enode * 64 + ej] = val;
                else           *(float2*)&sP[er * 64 + ej]           = val;
            }
        }

        // ---- grid barrier split into arrive / (stage next sW) / wait ----
        if (k > 0) {
            // release: EVERY thread fences its own d_B stores to device scope
            __threadfence();
            __syncthreads();              // all stores issued; sW no longer read
            unsigned int gen = 0;
            if (tid == 0) {
                gen = d_bar_gen;
                if (atomicAdd(&d_bar_count, 1u) == CB_GRID - 1u) {
                    d_bar_count = 0;
                    __threadfence();
                    d_bar_gen = gen + 1;
                }
            }
            // hide next step's Wc staging under the barrier wait
            {
                const float4* Wsrc = (const float4*)(d_Wc + (k - 1) * FF * 64);
                float4* Wdst = (float4*)sW;
                #pragma unroll
                for (int r = 0; r < 4; r++) {
                    int idx = r * CB_THREADS + tid;
                    Wdst[idx] = __ldg(&Wsrc[idx]);
                }
            }
            if (tid == 0) {
                while (d_bar_gen == gen) { }
                __threadfence();          // acquire
            }
            __syncthreads();
        }
    }

    // ---- fused tail: GRU gates + xp = h @ W_gat + attention scalars ----
    // Block-local: sP holds this block's 68 pre-activation rows. No grid sync.
    __syncthreads();
    #pragma unroll
    for (int rep = 0; rep < 5; rep++) {
        int li = rep * 16 + wrp;
        if (li >= CB_NODES) break;
        int node = nb + li;
        if (node >= NN) continue;
        float az = sP[li * 64 + lane];
        float ah = sP[li * 64 + 32 + lane];
        float z  = 1.f / (1.f + expf(-az));
        float hj = (1.f - z) * tanhf(ah);        // h = (1-Z)*Ht  (H0 == 0)
        float xpj = 0.f;
        #pragma unroll
        for (int c = 0; c < 32; c++) {
            float hc = __shfl_sync(0xffffffffu, hj, c);
            xpj += hc * __ldg(&Wg[c * 32 + lane]);
        }
        d_xp[node * 32 + lane] = xpj;
        float sa = xpj * __ldg(&a_src[lane]);
        float sd = xpj * __ldg(&a_dst[lane]);
        #pragma unroll
        for (int o = 16; o; o >>= 1) {
            sa += __shfl_xor_sync(0xffffffffu, sa, o);
            sd += __shfl_xor_sync(0xffffffffu, sd, o);
        }
        if (lane == 0) { d_as[node] = sa; d_ad[node] = sd; }
    }
}

__device__ __forceinline__ float lrelu(float v) { return v < 0.f ? 0.2f * v : v; }

// GAT online-softmax aggregate (2-edge unrolled) + relu + fold into (s,t)
// scalars. One warp per dst node. Logits are lane-invariant.
__global__ void k_gat(const float* __restrict__ bgat) {
    int w = (blockIdx.x * blockDim.x + threadIdx.x) >> 5;
    int lane = threadIdx.x & 31;
    if (w >= NN) return;
    float adi = d_ad[w];
    int rs = d_rowptr[w], re = d_rowptr[w + 1];

    // self loop initializes the running state: m = e0, den = 1, acc = xp[w]
    float m = lrelu(d_as[w] + adi);
    float den = 1.f;
    float accj = d_xp[w * 32 + lane];

    int e = rs;
    for (; e + 2 <= re; e += 2) {
        int s0 = __ldg(&d_edge[e]).x;
        int s1 = __ldg(&d_edge[e + 1]).x;
        float v0 = lrelu(d_as[s0] + adi);
        float v1 = lrelu(d_as[s1] + adi);
        float x0 = d_xp[s0 * 32 + lane];
        float x1 = d_xp[s1 * 32 + lane];
        float nm = fmaxf(m, fmaxf(v0, v1));
        float scale = expf(m - nm);      // 1 when no new max
        float wt0 = expf(v0 - nm);
        float wt1 = expf(v1 - nm);
        den = den * scale + wt0 + wt1;
        accj = accj * scale + wt0 * x0 + wt1 * x1;
        m = nm;
    }
    if (e < re) {
        int s0 = __ldg(&d_edge[e]).x;
        float v = lrelu(d_as[s0] + adi);
        float nm = fmaxf(m, v);
        float scale = expf(m - nm);
        float wt = expf(v - nm);
        den = den * scale + wt;
        accj = accj * scale + wt * d_xp[s0 * 32 + lane];
        m = nm;
    }

    float h2 = fmaxf(accj / den + bgat[lane], 0.f);
    float sv = h2 * d_pq[lane];
    float tv = h2 * d_pq[32 + lane];
    #pragma unroll
    for (int o = 16; o; o >>= 1) {
        sv += __shfl_xor_sync(0xffffffffu, sv, o);
        tv += __shfl_xor_sync(0xffffffffu, tv, o);
    }
    if (lane == 0) { d_sv[w] = sv + d_pq[64]; d_tv[w] = tv + d_pq[65]; }
}

__global__ void k_logit(const int* __restrict__ src, const int* __restrict__ dst,
                        float* __restrict__ out) {
    int e = (blockIdx.x * blockDim.x + threadIdx.x) * 2;
    if (e + 1 < EE) {
        int s0 = __ldg(&src[e]),     s1 = __ldg(&src[e + 1]);
        int d0 = __ldg(&dst[e]),     d1 = __ldg(&dst[e + 1]);
        float2 o;
        o.x = d_sv[s0] + d_tv[d0];
        o.y = d_sv[s1] + d_tv[d1];
        *(float2*)&out[e] = o;
    } else if (e < EE) {
        out[e] = d_sv[__ldg(&src[e])] + d_tv[__ldg(&dst[e])];
    }
}

// ---------------- host launcher ----------------
extern "C" void kernel_launch(void* const* d_in, const int* in_sizes, int n_in,
                              void* d_out, int out_size) {
    const float *x = 0, *Wxz = 0, *Wxh = 0;
    const float *bxz = 0, *bhz = 0, *bxh = 0, *bhh = 0;
    const float *a_src = 0, *a_dst = 0, *bgat = 0;
    const float *Wg = 0, *Wemb = 0, *bemb = 0, *Wcls = 0, *bcls = 0;
    const int* eidx = 0;
    int c131 = 0, c32 = 0;
    for (int i = 0; i < n_in; i++) {
        int sz = in_sizes[i];
        const float* p = (const float*)d_in[i];
        if (sz == 2560000) x = p;
        else if (sz == 640000) eidx = (const int*)d_in[i];
        else if (sz == 131072) { if (c131 == 0) Wxz = p; else if (c131 == 2) Wxh = p; c131++; }
        else if (sz == 32768) { /* W_h* unused: H0 == 0 */ }
        else if (sz == 32) {
            switch (c32) {
                case 0: bxz = p; break; case 1: bhz = p; break;
                case 2: /*bxr*/ break;  case 3: /*bhr*/ break;
                case 4: bxh = p; break; case 5: bhh = p; break;
                case 6: a_src = p; break; case 7: a_dst = p; break;
                case 8: bgat = p; break;
            }
            c32++;
        }
        else if (sz == 1024) Wg = p;
        else if (sz == 4096) Wemb = p;
        else if (sz == 128)  bemb = p;
        else if (sz == 256)  Wcls = p;
        else if (sz == 1)    bcls = p;
    }
    const int* src = eidx;
    const int* dst = eidx + EE;
    float* out = (float*)d_out;

    const int SMEM = (CB_NODES * FF + FF * 64 + CB_NODES * 64) * 4;   // 84992 B
    cudaFuncSetAttribute(cheb_persistent, cudaFuncAttributeMaxDynamicSharedMemorySize, SMEM);

    k_zero<<<(NN + 255) / 256, 256>>>();
    k_count<<<(EE + 255) / 256, 256>>>(src, dst);
    k_scan<<<1, 1024>>>();
    k_fill<<<(EE + 255) / 256, 256>>>(src, dst);
    k_sortrows<<<(NN + 7) / 8, 256>>>();
    k_weights<<<KORD + 2, 256>>>(Wxz, Wxh, bxz, bhz, bxh, bhh, Wemb, bemb, Wcls, bcls);

    // all 32 Clenshaw steps + GRU/GAT-linear tail in ONE persistent launch
    cheb_persistent<<<CB_GRID, CB_THREADS, SMEM>>>(x, Wg, a_src, a_dst);

    k_gat<<<(NN * 32 + 255) / 256, 256>>>(bgat);
    k_logit<<<(EE / 2 + 255) / 256, 256>>>(src, dst, out);
}

// round 17
// speedup vs baseline: 1.2199x; 1.2199x over previous
#include <cuda_runtime.h>
#include <math.h>

#define NN 20000
#define EE 320000
#define FF 128
#define KORD 32

// ---------------- device scratch (static: no allocations allowed) ----------------
__device__ __align__(16) float d_B[3][NN * 64];      // Clenshaw b-state ring (N x 64)
__device__ __align__(16) float d_bias[64];
__device__ __align__(16) float d_Wc[KORD * FF * 64]; // packed [W_xz[k] | W_xh[k]] per k
__device__ int   d_rowptr[NN + 1];
__device__ int   d_cnt[NN];
__device__ int   d_fill[NN];
__device__ int   d_deg[NN];
__device__ __align__(16) int2 d_edge[EE];            // (src, weight-bits) per CSR slot
__device__ float d_xp[NN * 32];
__device__ float d_as[NN];
__device__ float d_ad[NN];
__device__ float d_sv[NN];
__device__ float d_tv[NN];
__device__ float d_pq[66];   // [0..31]=p, [32..63]=q, [64]=cs+b_cls, [65]=ct
// software grid barrier state (reset every kernel_launch in k_zero)
__device__ unsigned int d_bar_count;
__device__ volatile unsigned int d_bar_gen;

// ---- packed f32x2 helpers (Blackwell dual-FMA pipe) ----
#define PACK2(dst, lo, hi) \
    asm("mov.b64 %0, {%1, %2};" : "=l"(dst) : "r"(__float_as_uint(lo)), "r"(__float_as_uint(hi)))
#define DUP2(dst, v) \
    asm("mov.b64 %0, {%1, %1};" : "=l"(dst) : "r"(__float_as_uint(v)))
#define FMA2(acc, a, b) \
    asm("fma.rn.f32x2 %0, %1, %2, %0;" : "+l"(acc) : "l"(a), "l"(b))
#define UNPACK2(lo, hi, v) do { unsigned int _ulo, _uhi; \
    asm("mov.b64 {%0, %1}, %2;" : "=r"(_ulo), "=r"(_uhi) : "l"(v)); \
    lo = __uint_as_float(_ulo); hi = __uint_as_float(_uhi); } while (0)

// ---------------- setup kernels ----------------
__global__ void k_zero() {
    int i = blockIdx.x * blockDim.x + threadIdx.x;
    if (i < NN) { d_deg[i] = 0; d_cnt[i] = 0; d_fill[i] = 0; }
    if (i == 0) { d_bar_count = 0; d_bar_gen = 0; }
}

__global__ void k_count(const int* __restrict__ src, const int* __restrict__ dst) {
    int e = blockIdx.x * blockDim.x + threadIdx.x;
    if (e < EE) {
        atomicAdd(&d_deg[src[e]], 1);
        atomicAdd(&d_cnt[dst[e]], 1);
    }
}

// single block, 1024 threads, 20 elements per thread + one Hillis-Steele pass
#define SCAN_CHUNK 20
__global__ void k_scan() {
    __shared__ int tot[1024];
    int tid = threadIdx.x;
    int base = tid * SCAN_CHUNK;
    int loc[SCAN_CHUNK];
    int s = 0;
    #pragma unroll
    for (int i = 0; i < SCAN_CHUNK; i++) {
        int idx = base + i;
        int v = (idx < NN) ? d_cnt[idx] : 0;
        loc[i] = s;
        s += v;
    }
    tot[tid] = s;
    __syncthreads();
    for (int off = 1; off < 1024; off <<= 1) {
        int t = (tid >= off) ? tot[tid - off] : 0;
        __syncthreads();
        tot[tid] += t;
        __syncthreads();
    }
    int excl = tot[tid] - s;
    #pragma unroll
    for (int i = 0; i < SCAN_CHUNK; i++) {
        int idx = base + i;
        if (idx < NN) d_rowptr[idx] = excl + loc[i];
    }
    if (tid == 1023) d_rowptr[NN] = tot[1023];
}

// CSR fill with inline symmetric-normalized weight:
// w = -1/sqrt(deg[s]) * 1/sqrt(deg[d]); deg[s] >= 1 since s sources edge e.
__global__ void k_fill(const int* __restrict__ src, const int* __restrict__ dst) {
    int e = blockIdx.x * blockDim.x + threadIdx.x;
    if (e < EE) {
        int d = dst[e], s = src[e];
        int pos = d_rowptr[d] + atomicAdd(&d_fill[d], 1);
        int degs = d_deg[s], degd = d_deg[d];
        float ws = 1.0f / sqrtf((float)degs);
        float wd = (degd > 0) ? (1.0f / sqrtf((float)degd)) : 0.0f;
        d_edge[pos] = make_int2(s, __float_as_int(-ws * wd));
    }
}

// warp-per-row rank sort (by src key) in shared memory: deterministic order.
#define SORT_CAP 128
__global__ void k_sortrows() {
    __shared__ int skey[8][SORT_CAP];
    __shared__ int sval[8][SORT_CAP];
    int wrp = threadIdx.x >> 5, lane = threadIdx.x & 31;
    int row = blockIdx.x * 8 + wrp;
    if (row >= NN) return;
    int rs = d_rowptr[row], re = d_rowptr[row + 1];
    int d = re - rs;
    if (d <= 1) return;
    if (d > SORT_CAP) {                 // practically unreachable fallback
        if (lane == 0) {
            for (int a = rs + 1; a < re; a++) {
                int2 key = d_edge[a];
                int b = a - 1;
                while (b >= rs && d_edge[b].x > key.x) {
                    d_edge[b + 1] = d_edge[b]; b--;
                }
                d_edge[b + 1] = key;
            }
        }
        return;
    }
    for (int i = lane; i < d; i += 32) {
        int2 q = d_edge[rs + i];
        skey[wrp][i] = q.x;
        sval[wrp][i] = q.y;
    }
    __syncwarp();
    for (int i = lane; i < d; i += 32) {
        int k = skey[wrp][i];
        int r = 0;
        for (int j = 0; j < d; j++) {
            int kj = skey[wrp][j];
            r += (kj < k) || (kj == k && j < i);
        }
        d_edge[rs + r] = make_int2(k, sval[wrp][i]);
    }
}

// merged weight-prep: blocks 0..31 pack Wc_k; block 32 bias; block 33 pq scalars
__global__ void k_weights(const float* __restrict__ Wxz, const float* __restrict__ Wxh,
                          const float* __restrict__ bxz, const float* __restrict__ bhz,
                          const float* __restrict__ bxh, const float* __restrict__ bhh,
                          const float* __restrict__ Wemb, const float* __restrict__ bemb,
                          const float* __restrict__ Wcls, const float* __restrict__ bcls) {
    int b = blockIdx.x;
    if (b < KORD) {
        const float* Wz = Wxz + b * FF * 32;
        const float* Wh = Wxh + b * FF * 32;
        float* out = d_Wc + b * FF * 64;
        for (int idx = threadIdx.x; idx < FF * 64; idx += blockDim.x) {
            int c = idx >> 6, j = idx & 63;
            out[idx] = (j < 32) ? __ldg(&Wz[c * 32 + j]) : __ldg(&Wh[c * 32 + j - 32]);
        }
    } else if (b == KORD) {
        int j = threadIdx.x;
        if (j < 32) d_bias[j] = bxz[j] + bhz[j];
        else if (j < 64) d_bias[j] = bxh[j - 32] + bhh[j - 32];
    } else {
        int t = threadIdx.x;
        if (t < 32) {
            float s = 0.f;
            for (int d = 0; d < 128; d++) s += Wemb[t * 128 + d] * Wcls[d];
            d_pq[t] = s;
        } else if (t < 64) {
            int j = t - 32; float s = 0.f;
            for (int d = 0; d < 128; d++) s += Wemb[j * 128 + d] * Wcls[128 + d];
            d_pq[32 + j] = s;
        } else if (t == 64) {
            float s = 0.f;
            for (int d = 0; d < 128; d++) s += bemb[d] * Wcls[d];
            d_pq[64] = s + bcls[0];
        } else if (t == 65) {
            float s = 0.f;
            for (int d = 0; d < 128; d++) s += bemb[d] * Wcls[128 + d];
            d_pq[65] = s;
        }
    }
}

// ---------------- persistent Clenshaw kernel + fused GRU/GAT-linear tail ----
// b_k = 2*Lhat*b_{k+1} - b_{k+2} + X*Wc_k   (k = 31 .. 1;  b_32 = b_33 = 0)
// out = 1*Lhat*b_1 - b_2 + X*Wc_0 + bias    (k = 0, kept in smem sP)
// Gather and GEMM-accumulate are NOT separated by a barrier: per-warp gather
// overlaps other warps' FMA work; single sync before the sP-combine.
// GEMM thread tile = 4 rows x 2 cols: each 8B sW load feeds 4 FMA2.
#define CB_NODES 68
#define CB_THREADS 512
#define CB_GRID 295

__global__ void __launch_bounds__(CB_THREADS, 2)
cheb_persistent(const float* __restrict__ x,
                const float* __restrict__ Wg,
                const float* __restrict__ a_src,
                const float* __restrict__ a_dst)
{
    extern __shared__ float sm[];
    float* sX = sm;                        // 68 x 128  (loop-invariant)
    float* sW = sX + CB_NODES * FF;        // 128 x 64
    float* sP = sW + FF * 64;              // 68 x 64
    const int tid  = threadIdx.x;
    const int lane = tid & 31;
    const int wrp  = tid >> 5;             // 0..15
    const int nb   = blockIdx.x * CB_NODES;

    // GEMM tile coords: 4 rows x 2 cols per thread
    const int tx = tid & 31, ty = tid >> 5;
    const int j0 = tx * 2, r0 = ty * 4;
    // remainder coords: rows 64..67, threads 0..127, 1 row x 2 cols
    const bool has_rem = (tid < 128);
    const int er = 64 + (tid >> 5);        // valid when has_rem (64..67)
    const int ej = (tid & 31) * 2;
    const int enode = nb + er;

    // stage x tile ONCE (loop-invariant) and Wc for the first step (k=31)
    #pragma unroll
    for (int rep = 0; rep < 5; rep++) {
        int li = rep * 16 + wrp;
        if (li >= CB_NODES) break;
        int node = nb + li;
        float4 v = make_float4(0.f, 0.f, 0.f, 0.f);
        if (node < NN) v = __ldg((const float4*)&x[node * FF + lane * 4]);
        *(float4*)&sX[li * FF + lane * 4] = v;
    }
    {
        const float4* Wsrc = (const float4*)(d_Wc + (KORD - 1) * FF * 64);
        float4* Wdst = (float4*)sW;
        #pragma unroll
        for (int r = 0; r < 4; r++) {
            int idx = r * CB_THREADS + tid;     // 2048 float4s
            Wdst[idx] = __ldg(&Wsrc[idx]);
        }
    }
    __syncthreads();   // sX + first sW visible to all

    for (int k = KORD - 1; k >= 0; k--) {
        const int gsel  = (k <= 30) ? (k + 1) % 3 : -1;   // buffer holding b_{k+1}
        const int ppsel = (k <= 29) ? (k + 2) % 3 : -1;   // buffer holding b_{k+2}
        const int nsel  = (k >= 1) ? (k % 3) : -1;        // write b_k (smem at k=0)
        const float coef = (k == 0) ? 1.f : 2.f;

        // ---- gather phase: prop rows of b_{k+1}; warp per node ----
        if (gsel >= 0) {
            const float* Bg = d_B[gsel];
            #pragma unroll
            for (int rep = 0; rep < 5; rep++) {
                int li = rep * 16 + wrp;
                if (li >= CB_NODES) break;
                int node = nb + li;
                float2 a = make_float2(0.f, 0.f);
                if (node < NN) {
                    int rs = d_rowptr[node], re = d_rowptr[node + 1];
                    int e = rs;
                    for (; e + 4 <= re; e += 4) {
                        int2 q0 = __ldg(&d_edge[e]);
                        int2 q1 = __ldg(&d_edge[e + 1]);
                        int2 q2 = __ldg(&d_edge[e + 2]);
                        int2 q3 = __ldg(&d_edge[e + 3]);
                        float2 v0 = __ldcg((const float2*)&Bg[q0.x * 64 + lane * 2]);
                        float2 v1 = __ldcg((const float2*)&Bg[q1.x * 64 + lane * 2]);
                        float2 v2 = __ldcg((const float2*)&Bg[q2.x * 64 + lane * 2]);
                        float2 v3 = __ldcg((const float2*)&Bg[q3.x * 64 + lane * 2]);
                        float w0 = __int_as_float(q0.y), w1 = __int_as_float(q1.y);
                        float w2 = __int_as_float(q2.y), w3 = __int_as_float(q3.y);
                        a.x += w0 * v0.x + w1 * v1.x + w2 * v2.x + w3 * v3.x;
                        a.y += w0 * v0.y + w1 * v1.y + w2 * v2.y + w3 * v3.y;
                    }
                    for (; e < re; e++) {
                        int2 q = __ldg(&d_edge[e]);
                        float2 v = __ldcg((const float2*)&Bg[q.x * 64 + lane * 2]);
                        float w = __int_as_float(q.y);
                        a.x += w * v.x; a.y += w * v.y;
                    }
                }
                *(float2*)&sP[li * 64 + lane * 2] = a;
            }
        }

        // ---- GEMM accumulate (reads only sX/sW — overlaps other warps' gather) ----
        float2 pre[4];
        #pragma unroll
        for (int i = 0; i < 4; i++) {
            pre[i] = make_float2(0.f, 0.f);
            int node = nb + r0 + i;
            if (ppsel >= 0 && node < NN) {
                float2 t = __ldcg((const float2*)&d_B[ppsel][node * 64 + j0]);
                pre[i].x = -t.x; pre[i].y = -t.y;
            }
            if (nsel < 0) { pre[i].x += d_bias[j0]; pre[i].y += d_bias[j0 + 1]; }
        }
        unsigned long long c0, c1, c2, c3;
        PACK2(c0, pre[0].x, pre[0].y);
        PACK2(c1, pre[1].x, pre[1].y);
        PACK2(c2, pre[2].x, pre[2].y);
        PACK2(c3, pre[3].x, pre[3].y);

        const float* rA0 = &sX[(r0 + 0) * FF];
        const float* rA1 = &sX[(r0 + 1) * FF];
        const float* rA2 = &sX[(r0 + 2) * FF];
        const float* rA3 = &sX[(r0 + 3) * FF];
        #pragma unroll 4
        for (int kk = 0; kk < 128; kk += 4) {
            float4 v0 = *(const float4*)&rA0[kk];
            float4 v1 = *(const float4*)&rA1[kk];
            float4 v2 = *(const float4*)&rA2[kk];
            float4 v3 = *(const float4*)&rA3[kk];
            unsigned long long b, a;
            b = *(const unsigned long long*)&sW[(kk + 0) * 64 + j0];
            DUP2(a, v0.x); FMA2(c0, a, b);
            DUP2(a, v1.x); FMA2(c1, a, b);
            DUP2(a, v2.x); FMA2(c2, a, b);
            DUP2(a, v3.x); FMA2(c3, a, b);
            b = *(const unsigned long long*)&sW[(kk + 1) * 64 + j0];
            DUP2(a, v0.y); FMA2(c0, a, b);
            DUP2(a, v1.y); FMA2(c1, a, b);
            DUP2(a, v2.y); FMA2(c2, a, b);
            DUP2(a, v3.y); FMA2(c3, a, b);
            b = *(const unsigned long long*)&sW[(kk + 2) * 64 + j0];
            DUP2(a, v0.z); FMA2(c0, a, b);
            DUP2(a, v1.z); FMA2(c1, a, b);
            DUP2(a, v2.z); FMA2(c2, a, b);
            DUP2(a, v3.z); FMA2(c3, a, b);
            b = *(const unsigned long long*)&sW[(kk + 3) * 64 + j0];
            DUP2(a, v0.w); FMA2(c0, a, b);
            DUP2(a, v1.w); FMA2(c1, a, b);
            DUP2(a, v2.w); FMA2(c2, a, b);
            DUP2(a, v3.w); FMA2(c3, a, b);
        }

        // ---- remainder accumulate: rows 64..67 (threads 0..127) ----
        unsigned long long cc = 0;
        if (has_rem && enode < NN) {
            float2 prer = make_float2(0.f, 0.f);
            if (ppsel >= 0) {
                float2 t = __ldcg((const float2*)&d_B[ppsel][enode * 64 + ej]);
                prer.x = -t.x; prer.y = -t.y;
            }
            if (nsel < 0) { prer.x += d_bias[ej]; prer.y += d_bias[ej + 1]; }
            PACK2(cc, prer.x, prer.y);
            const float* rowE = &sX[er * FF];
            #pragma unroll 8
            for (int kk = 0; kk < 128; kk++) {
                unsigned long long a, b;
                DUP2(a, rowE[kk]);
                b = *(const unsigned long long*)&sW[kk * 64 + ej];
                FMA2(cc, a, b);
            }
        }

        __syncthreads();    // all sP gather writes complete; sW reads done

        // ---- combine with sP + store ----
        {
            float2 r[4];
            UNPACK2(r[0].x, r[0].y, c0);
            UNPACK2(r[1].x, r[1].y, c1);
            UNPACK2(r[2].x, r[2].y, c2);
            UNPACK2(r[3].x, r[3].y, c3);
            #pragma unroll
            for (int i = 0; i < 4; i++) {
                int node = nb + r0 + i;
                if (node >= NN) continue;
                float2 val = r[i];
                if (gsel >= 0) {
                    float2 p = *(const float2*)&sP[(r0 + i) * 64 + j0];
                    val.x += coef * p.x; val.y += coef * p.y;
                }
                if (nsel >= 0) *(float2*)&d_B[nsel][node * 64 + j0] = val;
                else           *(float2*)&sP[(r0 + i) * 64 + j0]    = val;  // k=0
            }
        }
        if (has_rem && enode < NN) {
            float2 val;
            UNPACK2(val.x, val.y, cc);
            if (gsel >= 0) {
                float2 p = *(const float2*)&sP[er * 64 + ej];
                val.x += coef * p.x; val.y += coef * p.y;
            }
            if (nsel >= 0) *(float2*)&d_B[nsel][enode * 64 + ej] = val;
            else           *(float2*)&sP[er * 64 + ej]           = val;
        }

        // ---- grid barrier: arrive / (stage next sW) / wait ----
        if (k > 0) {
            __threadfence();              // every thread fences its d_B stores
            __syncthreads();              // all stores issued; sW no longer read
            unsigned int gen = 0;
            if (tid == 0) {
                gen = d_bar_gen;
                if (atomicAdd(&d_bar_count, 1u) == CB_GRID - 1u) {
                    d_bar_count = 0;
                    __threadfence();
                    d_bar_gen = gen + 1;
                }
            }
            // hide next step's Wc staging under the barrier wait
            {
                const float4* Wsrc = (const float4*)(d_Wc + (k - 1) * FF * 64);
                float4* Wdst = (float4*)sW;
                #pragma unroll
                for (int r = 0; r < 4; r++) {
                    int idx = r * CB_THREADS + tid;
                    Wdst[idx] = __ldg(&Wsrc[idx]);
                }
            }
            if (tid == 0) {
                while (d_bar_gen == gen) { }
                __threadfence();          // acquire
            }
            __syncthreads();
        }
    }

    // ---- fused tail: GRU gates + xp = h @ W_gat + attention scalars ----
    __syncthreads();
    #pragma unroll
    for (int rep = 0; rep < 5; rep++) {
        int li = rep * 16 + wrp;
        if (li >= CB_NODES) break;
        int node = nb + li;
        if (node >= NN) continue;
        float az = sP[li * 64 + lane];
        float ah = sP[li * 64 + 32 + lane];
        float z  = 1.f / (1.f + expf(-az));
        float hj = (1.f - z) * tanhf(ah);        // h = (1-Z)*Ht  (H0 == 0)
        float xpj = 0.f;
        #pragma unroll
        for (int c = 0; c < 32; c++) {
            float hc = __shfl_sync(0xffffffffu, hj, c);
            xpj += hc * __ldg(&Wg[c * 32 + lane]);
        }
        d_xp[node * 32 + lane] = xpj;
        float sa = xpj * __ldg(&a_src[lane]);
        float sd = xpj * __ldg(&a_dst[lane]);
        #pragma unroll
        for (int o = 16; o; o >>= 1) {
            sa += __shfl_xor_sync(0xffffffffu, sa, o);
            sd += __shfl_xor_sync(0xffffffffu, sd, o);
        }
        if (lane == 0) { d_as[node] = sa; d_ad[node] = sd; }
    }
}

__device__ __forceinline__ float lrelu(float v) { return v < 0.f ? 0.2f * v : v; }

// GAT online-softmax aggregate (2-edge unrolled) + relu + fold into (s,t)
// scalars. One warp per dst node. Logits are lane-invariant.
__global__ void k_gat(const float* __restrict__ bgat) {
    int w = (blockIdx.x * blockDim.x + threadIdx.x) >> 5;
    int lane = threadIdx.x & 31;
    if (w >= NN) return;
    float adi = d_ad[w];
    int rs = d_rowptr[w], re = d_rowptr[w + 1];

    // self loop initializes the running state: m = e0, den = 1, acc = xp[w]
    float m = lrelu(d_as[w] + adi);
    float den = 1.f;
    float accj = d_xp[w * 32 + lane];

    int e = rs;
    for (; e + 2 <= re; e += 2) {
        int s0 = __ldg(&d_edge[e]).x;
        int s1 = __ldg(&d_edge[e + 1]).x;
        float v0 = lrelu(d_as[s0] + adi);
        float v1 = lrelu(d_as[s1] + adi);
        float x0 = d_xp[s0 * 32 + lane];
        float x1 = d_xp[s1 * 32 + lane];
        float nm = fmaxf(m, fmaxf(v0, v1));
        float scale = expf(m - nm);      // 1 when no new max
        float wt0 = expf(v0 - nm);
        float wt1 = expf(v1 - nm);
        den = den * scale + wt0 + wt1;
        accj = accj * scale + wt0 * x0 + wt1 * x1;
        m = nm;
    }
    if (e < re) {
        int s0 = __ldg(&d_edge[e]).x;
        float v = lrelu(d_as[s0] + adi);
        float nm = fmaxf(m, v);
        float scale = expf(m - nm);
        float wt = expf(v - nm);
        den = den * scale + wt;
        accj = accj * scale + wt * d_xp[s0 * 32 + lane];
        m = nm;
    }

    float h2 = fmaxf(accj / den + bgat[lane], 0.f);
    float sv = h2 * d_pq[lane];
    float tv = h2 * d_pq[32 + lane];
    #pragma unroll
    for (int o = 16; o; o >>= 1) {
        sv += __shfl_xor_sync(0xffffffffu, sv, o);
        tv += __shfl_xor_sync(0xffffffffu, tv, o);
    }
    if (lane == 0) { d_sv[w] = sv + d_pq[64]; d_tv[w] = tv + d_pq[65]; }
}

__global__ void k_logit(const int* __restrict__ src, const int* __restrict__ dst,
                        float* __restrict__ out) {
    int e = (blockIdx.x * blockDim.x + threadIdx.x) * 2;
    if (e + 1 < EE) {
        int s0 = __ldg(&src[e]),     s1 = __ldg(&src[e + 1]);
        int d0 = __ldg(&dst[e]),     d1 = __ldg(&dst[e + 1]);
        float2 o;
        o.x = d_sv[s0] + d_tv[d0];
        o.y = d_sv[s1] + d_tv[d1];
        *(float2*)&out[e] = o;
    } else if (e < EE) {
        out[e] = d_sv[__ldg(&src[e])] + d_tv[__ldg(&dst[e])];
    }
}

// ---------------- host launcher ----------------
extern "C" void kernel_launch(void* const* d_in, const int* in_sizes, int n_in,
                              void* d_out, int out_size) {
    const float *x = 0, *Wxz = 0, *Wxh = 0;
    const float *bxz = 0, *bhz = 0, *bxh = 0, *bhh = 0;
    const float *a_src = 0, *a_dst = 0, *bgat = 0;
    const float *Wg = 0, *Wemb = 0, *bemb = 0, *Wcls = 0, *bcls = 0;
    const int* eidx = 0;
    int c131 = 0, c32 = 0;
    for (int i = 0; i < n_in; i++) {
        int sz = in_sizes[i];
        const float* p = (const float*)d_in[i];
        if (sz == 2560000) x = p;
        else if (sz == 640000) eidx = (const int*)d_in[i];
        else if (sz == 131072) { if (c131 == 0) Wxz = p; else if (c131 == 2) Wxh = p; c131++; }
        else if (sz == 32768) { /* W_h* unused: H0 == 0 */ }
        else if (sz == 32) {
            switch (c32) {
                case 0: bxz = p; break; case 1: bhz = p; break;
                case 2: /*bxr*/ break;  case 3: /*bhr*/ break;
                case 4: bxh = p; break; case 5: bhh = p; break;
                case 6: a_src = p; break; case 7: a_dst = p; break;
                case 8: bgat = p; break;
            }
            c32++;
        }
        else if (sz == 1024) Wg = p;
        else if (sz == 4096) Wemb = p;
        else if (sz == 128)  bemb = p;
        else if (sz == 256)  Wcls = p;
        else if (sz == 1)    bcls = p;
    }
    const int* src = eidx;
    const int* dst = eidx + EE;
    float* out = (float*)d_out;

    const int SMEM = (CB_NODES * FF + FF * 64 + CB_NODES * 64) * 4;   // 84992 B
    cudaFuncSetAttribute(cheb_persistent, cudaFuncAttributeMaxDynamicSharedMemorySize, SMEM);

    k_zero<<<(NN + 255) / 256, 256>>>();
    k_count<<<(EE + 255) / 256, 256>>>(src, dst);
    k_scan<<<1, 1024>>>();
    k_fill<<<(EE + 255) / 256, 256>>>(src, dst);
    k_sortrows<<<(NN + 7) / 8, 256>>>();
    k_weights<<<KORD + 2, 256>>>(Wxz, Wxh, bxz, bhz, bxh, bhh, Wemb, bemb, Wcls, bcls);

    // all 32 Clenshaw steps + GRU/GAT-linear tail in ONE persistent launch
    cheb_persistent<<<CB_GRID, CB_THREADS, SMEM>>>(x, Wg, a_src, a_dst);

    k_gat<<<(NN * 32 + 255) / 256, 256>>>(bgat);
    k_logit<<<(EE / 2 + 255) / 256, 256>>>(src, dst, out);
}